// round 6
// baseline (speedup 1.0000x reference)
#include <cuda_runtime.h>

#define NV 5
#define NC 32
#define ND 48
#define NH 128
#define NW 160
#define HW (NH*NW)        /* 20480 */
#define DHW (ND*HW)       /* 983040 */
#define RATIO 8

// Scratch (device globals — no allocation allowed)
__device__ float g_feat[NV*HW*NC];          // (v, h, w, c) channels-last fp32, 13.1 MB
__device__ float g_B[(size_t)9*DHW];        // 9 hw-tap fields (kd folded), 35.4 MB
__device__ float g_pre[DHW];                // (d, h, w), 3.9 MB
__device__ float g_rot[NV][9];
__device__ float g_trans[NV][3];

// Conv weights, layout [c*27 + kd*9 + tap9] — warp-uniform reads (LDC/LDCU path)
__constant__ float c_W[NC*27];

// ---------------------------------------------------------------------------
// 1) Projection setup (trivial)
// ---------------------------------------------------------------------------
__global__ void proj_kernel(const float* __restrict__ proj) {
    if (threadIdx.x != 0) return;
    float comb[NV][16];
    for (int v = 0; v < NV; v++) {
        const float* E = proj + v*32;
        const float* P = proj + v*32 + 16;
        for (int r = 0; r < 3; r++)
            for (int c = 0; c < 4; c++) {
                float s = 0.f;
                for (int k = 0; k < 3; k++) s += P[r*4+k] * E[k*4+c];
                comb[v][r*4+c] = s;
            }
        for (int c = 0; c < 4; c++) comb[v][12+c] = E[12+c];
    }
    float a[4][8];
    for (int i = 0; i < 4; i++)
        for (int j = 0; j < 4; j++) { a[i][j] = comb[0][i*4+j]; a[i][4+j] = (i==j) ? 1.f : 0.f; }
    for (int col = 0; col < 4; col++) {
        int p = col;
        for (int r = col+1; r < 4; r++) if (fabsf(a[r][col]) > fabsf(a[p][col])) p = r;
        if (p != col) for (int j = 0; j < 8; j++) { float t = a[col][j]; a[col][j] = a[p][j]; a[p][j] = t; }
        float inv = 1.f / a[col][col];
        for (int j = 0; j < 8; j++) a[col][j] *= inv;
        for (int r = 0; r < 4; r++) if (r != col) {
            float f = a[r][col];
            for (int j = 0; j < 8; j++) a[r][j] -= f * a[col][j];
        }
    }
    for (int v = 1; v < NV; v++) {
        float Pm[16];
        for (int i = 0; i < 4; i++)
            for (int j = 0; j < 4; j++) {
                float s = 0.f;
                for (int k = 0; k < 4; k++) s += comb[v][i*4+k] * a[k][4+j];
                Pm[i*4+j] = s;
            }
        for (int i = 0; i < 3; i++) {
            for (int j = 0; j < 3; j++) g_rot[v][i*3+j] = Pm[i*4+j];
            g_trans[v][i] = Pm[i*4+3];
        }
    }
}

// ---------------------------------------------------------------------------
// 2) Features (V,C,H,W) -> (V,H,W,C) channels-last (fp32)
// ---------------------------------------------------------------------------
__global__ __launch_bounds__(256) void transpose_kernel(const float* __restrict__ f) {
    __shared__ float t[32][33];
    int w0 = blockIdx.x * 32, h = blockIdx.y, v = blockIdx.z;
    int tid = threadIdx.x;
    #pragma unroll
    for (int e = tid; e < 1024; e += 256) {
        int c = e >> 5, w = e & 31;
        t[c][w] = f[((size_t)(v*NC + c)*NH + h)*NW + w0 + w];
    }
    __syncthreads();
    #pragma unroll
    for (int e = tid; e < 1024; e += 256) {
        int w = e >> 5, c = e & 31;
        g_feat[((size_t)((v*NH + h)*NW) + w0 + w)*NC + c] = t[c][w];
    }
}

// ---------------------------------------------------------------------------
// 3) FUSED: warp + variance + channel contraction + conv-kd folding.
//    256 threads (8 warps), 2 CTAs/SM (no weight registers — weights come
//    from __constant__, warp-uniform).  Warp wid owns hw-tap wid (warp 0
//    also owns tap 8); ring accumulators fold conv's kd so only 9 tap-
//    fields hit memory.  One barrier per d via double-buffered smem.
// ---------------------------------------------------------------------------
__global__ __launch_bounds__(256, 2) void warpvar_kernel(const float* __restrict__ dvals) {
    int tid  = threadIdx.x;
    int lane = tid & 31, wid = tid >> 5;     // wid 0..7
    int sub = lane >> 3, q = lane & 7;
    int p  = wid * 4 + sub;                  // point 0..31
    int w0 = blockIdx.x * 32;
    int h  = blockIdx.y;
    int w  = w0 + p;

    __shared__ float sdep[ND];
    if (tid < ND) sdep[tid] = dvals[tid];

    // ---- per-view projection precompute ----
    float fw = (float)w, fh = (float)h;
    float rx[NV-1], ry[NV-1], rz[NV-1], tcx[NV-1], tcy[NV-1], tcz[NV-1];
    #pragma unroll
    for (int v = 1; v < NV; v++) {
        const float* R = g_rot[v];
        const float* T = g_trans[v];
        rx[v-1] = R[0]*fw + R[1]*fh + R[2];
        ry[v-1] = R[3]*fw + R[4]*fh + R[5];
        rz[v-1] = R[6]*fw + R[7]*fh + R[8];
        tcx[v-1] = T[0]; tcy[v-1] = T[1]; tcz[v-1] = T[2];
    }

    // ---- reference view contribution (depth-independent) ----
    const float4* f0 = (const float4*)(g_feat + (size_t)(h*NW + w)*NC) + q;
    float4 ref = *f0;
    float4 ref2 = make_float4(ref.x*ref.x, ref.y*ref.y, ref.z*ref.z, ref.w*ref.w);

    __shared__ float sv[2][32][33];
    const float inv5 = 1.f / (float)NV;

    __syncthreads();   // sdep ready

    auto compute_var = [&](float dep) -> float4 {
        float4 vs = ref;
        float4 vq = ref2;
        #pragma unroll
        for (int v = 0; v < NV-1; v++) {
            float px = rx[v]*dep + tcx[v];
            float py = ry[v]*dep + tcy[v];
            float pz = rz[v]*dep + tcz[v];
            float rzi = __fdividef(1.f, pz);
            float gx = px * rzi, gy = py * rzi;
            float x0f = floorf(gx), y0f = floorf(gy);
            float wx = gx - x0f, wy = gy - y0f;
            float x1f = x0f + 1.f, y1f = y0f + 1.f;
            float vx0 = (x0f >= 0.f && x0f <= (float)(NW-1)) ? 1.f : 0.f;
            float vx1 = (x1f >= 0.f && x1f <= (float)(NW-1)) ? 1.f : 0.f;
            float vy0 = (y0f >= 0.f && y0f <= (float)(NH-1)) ? 1.f : 0.f;
            float vy1 = (y1f >= 0.f && y1f <= (float)(NH-1)) ? 1.f : 0.f;
            float w00 = (1.f-wx)*(1.f-wy) * vx0 * vy0;
            float w10 = wx*(1.f-wy)       * vx1 * vy0;
            float w01 = (1.f-wx)*wy       * vx0 * vy1;
            float w11 = wx*wy             * vx1 * vy1;
            int x0 = (int)fminf(fmaxf(x0f, 0.f), (float)(NW-1));
            int x1 = (int)fminf(fmaxf(x1f, 0.f), (float)(NW-1));
            int y0 = (int)fminf(fmaxf(y0f, 0.f), (float)(NH-1));
            int y1 = (int)fminf(fmaxf(y1f, 0.f), (float)(NH-1));
            const float* base = g_feat + (size_t)(v+1)*HW*NC;
            float4 a  = ((const float4*)(base + (size_t)(y0*NW + x0)*NC))[q];
            float4 b  = ((const float4*)(base + (size_t)(y0*NW + x1)*NC))[q];
            float4 c4 = ((const float4*)(base + (size_t)(y1*NW + x0)*NC))[q];
            float4 e4 = ((const float4*)(base + (size_t)(y1*NW + x1)*NC))[q];
            float4 wv;
            wv.x = w00*a.x + w10*b.x + w01*c4.x + w11*e4.x;
            wv.y = w00*a.y + w10*b.y + w01*c4.y + w11*e4.y;
            wv.z = w00*a.z + w10*b.z + w01*c4.z + w11*e4.z;
            wv.w = w00*a.w + w10*b.w + w01*c4.w + w11*e4.w;
            vs.x += wv.x; vs.y += wv.y; vs.z += wv.z; vs.w += wv.w;
            vq.x += wv.x*wv.x; vq.y += wv.y*wv.y; vq.z += wv.z*wv.z; vq.w += wv.w*wv.w;
        }
        float mx = vs.x*inv5, my = vs.y*inv5, mz = vs.z*inv5, mw = vs.w*inv5;
        return make_float4(vq.x*inv5 - mx*mx, vq.y*inv5 - my*my,
                           vq.z*inv5 - mz*mz, vq.w*inv5 - mw*mw);
    };

    // ring accumulators (tap slot 0 = wid; slot 1 = tap 8, warp 0 only)
    float aP0 = 0.f, aC0 = 0.f, aN0 = 0.f;
    float aP1 = 0.f, aC1 = 0.f, aN1 = 0.f;
    const size_t hwbase = (size_t)h*NW + w0 + lane;

    for (int d = 0; d < ND; d++) {
        float4 vvar = compute_var(sdep[d]);
        int buf = d & 1;
        sv[buf][4*q+0][p] = vvar.x;
        sv[buf][4*q+1][p] = vvar.y;
        sv[buf][4*q+2][p] = vvar.z;
        sv[buf][4*q+3][p] = vvar.w;
        __syncthreads();

        // tap = wid: 3 kd-dots, weights from constant memory (warp-uniform)
        {
            float d0 = 0.f, d1 = 0.f, d2 = 0.f;
            #pragma unroll
            for (int c = 0; c < 32; c++) {
                float f = sv[buf][c][lane];
                d0 += f * c_W[c*27 + 0*9 + wid];
                d1 += f * c_W[c*27 + 1*9 + wid];
                d2 += f * c_W[c*27 + 2*9 + wid];
            }
            aN0 += d0; aC0 += d1; aP0 += d2;     // od = d+1, d, d-1
            if (d >= 1)
                g_B[(size_t)wid*DHW + (size_t)(d-1)*HW + hwbase] = aP0;
            aP0 = aC0; aC0 = aN0; aN0 = 0.f;
        }
        // tap = 8 on warp 0
        if (wid == 0) {
            float d0 = 0.f, d1 = 0.f, d2 = 0.f;
            #pragma unroll
            for (int c = 0; c < 32; c++) {
                float f = sv[buf][c][lane];
                d0 += f * c_W[c*27 + 0*9 + 8];
                d1 += f * c_W[c*27 + 1*9 + 8];
                d2 += f * c_W[c*27 + 2*9 + 8];
            }
            aN1 += d0; aC1 += d1; aP1 += d2;
            if (d >= 1)
                g_B[(size_t)8*DHW + (size_t)(d-1)*HW + hwbase] = aP1;
            aP1 = aC1; aC1 = aN1; aN1 = 0.f;
        }
    }
    // od = ND-1 completes after the last input plane
    g_B[(size_t)wid*DHW + (size_t)(ND-1)*HW + hwbase] = aP0;
    if (wid == 0)
        g_B[(size_t)8*DHW + (size_t)(ND-1)*HW + hwbase] = aP1;
}

// ---------------------------------------------------------------------------
// 4) 9-tap shifted sum over (h,w): pre[d,h,w] = sum_{kh,kw} B_t[d,h+kh-1,w+kw-1]
// ---------------------------------------------------------------------------
__global__ __launch_bounds__(256) void gathersum_kernel() {
    int w = blockIdx.x*32 + threadIdx.x;
    int h = blockIdx.y*8  + threadIdx.y;
    int d = blockIdx.z;
    float s = 0.f;
    #pragma unroll
    for (int kh = 0; kh < 3; kh++) {
        int hh = h + kh - 1;
        if (hh < 0 || hh >= NH) continue;
        size_t rowb = (size_t)d*HW + (size_t)hh*NW;
        #pragma unroll
        for (int kw = 0; kw < 3; kw++) {
            int ww = w + kw - 1;
            if (ww < 0 || ww >= NW) continue;
            int t = kh*3 + kw;
            s += g_B[(size_t)t*DHW + rowb + ww];
        }
    }
    g_pre[(size_t)d*HW + (size_t)h*NW + w] = s;
}

// ---------------------------------------------------------------------------
// 5) Softmax over D + depth regression + confidence
// ---------------------------------------------------------------------------
__global__ __launch_bounds__(256) void sdc_kernel(const float* __restrict__ dvals,
                                                  float* __restrict__ odepth,
                                                  float* __restrict__ oconf) {
    int idx = blockIdx.x*blockDim.x + threadIdx.x;
    if (idx >= HW) return;
    float p[ND];
    float mx = -1e30f;
    #pragma unroll
    for (int dd = 0; dd < ND; dd++) { p[dd] = g_pre[(size_t)dd*HW + idx]; mx = fmaxf(mx, p[dd]); }
    float s = 0.f;
    #pragma unroll
    for (int dd = 0; dd < ND; dd++) { p[dd] = expf(p[dd] - mx); s += p[dd]; }
    float inv = 1.f / s;
    float depth = 0.f, fi = 0.f;
    #pragma unroll
    for (int dd = 0; dd < ND; dd++) {
        float pr = p[dd] * inv;
        depth += pr * dvals[dd];
        fi    += pr * (float)dd;
    }
    int di = (int)fi;
    di = max(0, min(ND-1, di));
    float conf = 0.f;
    #pragma unroll
    for (int dd = 0; dd < ND; dd++)
        if (dd >= di-1 && dd <= di+2) conf += p[dd] * inv;
    odepth[idx] = depth;
    oconf[idx]  = conf;
}

// ---------------------------------------------------------------------------
// 6) Convex upsample x8
// ---------------------------------------------------------------------------
__global__ __launch_bounds__(256) void upsample_kernel(const float* __restrict__ mask,
                                                       const float* __restrict__ depth,
                                                       float* __restrict__ out) {
    int idx = blockIdx.x*blockDim.x + threadIdx.x;
    if (idx >= RATIO*HW) return;
    int i   = idx / HW;
    int rem = idx - i*HW;
    int h   = rem / NW;
    int w   = rem - h*NW;

    float nb[9];
    #pragma unroll
    for (int dy = 0; dy < 3; dy++)
        #pragma unroll
        for (int dx = 0; dx < 3; dx++) {
            int hh = h + dy - 1, ww = w + dx - 1;
            nb[dy*3+dx] = (hh >= 0 && hh < NH && ww >= 0 && ww < NW) ? depth[hh*NW + ww] : 0.f;
        }

    float val[8];
    #pragma unroll
    for (int j = 0; j < 8; j++) {
        float m[9]; float mx = -1e30f;
        #pragma unroll
        for (int k = 0; k < 9; k++) {
            m[k] = mask[(size_t)((k*8 + i)*8 + j)*HW + rem];
            mx = fmaxf(mx, m[k]);
        }
        float s = 0.f, acc = 0.f;
        #pragma unroll
        for (int k = 0; k < 9; k++) {
            float e = __expf(m[k] - mx);
            s += e; acc += e * nb[k];
        }
        val[j] = acc / s;
    }
    float* o = out + (size_t)(h*8 + i)*(NW*8) + w*8;
    float4* o4 = (float4*)o;
    o4[0] = make_float4(val[0], val[1], val[2], val[3]);
    o4[1] = make_float4(val[4], val[5], val[6], val[7]);
}

// ---------------------------------------------------------------------------
extern "C" void kernel_launch(void* const* d_in, const int* in_sizes, int n_in,
                              void* d_out, int out_size) {
    const float* features = (const float*)d_in[0];  // (V,B,C,H,W)
    const float* proj     = (const float*)d_in[1];  // (B,V,2,4,4)
    const float* dvals    = (const float*)d_in[2];  // (B,D)
    const float* mask     = (const float*)d_in[3];  // (B,576,H,W)
    const float* Wreg     = (const float*)d_in[4];  // (1,C,3,3,3)

    float* out       = (float*)d_out;
    float* out_depth = out + (size_t)NH*RATIO*NW*RATIO;   // after depth_up
    float* out_conf  = out_depth + HW;

    // conv weights -> constant memory (device-to-device async copy: allowed)
    cudaMemcpyToSymbolAsync(c_W, Wreg, NC*27*sizeof(float), 0,
                            cudaMemcpyDeviceToDevice, 0);

    proj_kernel<<<1, 32>>>(proj);
    transpose_kernel<<<dim3(NW/32, NH, NV), 256>>>(features);
    warpvar_kernel<<<dim3(NW/32, NH), 256>>>(dvals);
    gathersum_kernel<<<dim3(NW/32, NH/8, ND), dim3(32, 8)>>>();
    sdc_kernel<<<HW/256, 256>>>(dvals, out_depth, out_conf);
    upsample_kernel<<<(RATIO*HW)/256, 256>>>(mask, out_depth, out);
}

// round 7
// speedup vs baseline: 1.3589x; 1.3589x over previous
#include <cuda_runtime.h>

#define NV 5
#define NC 32
#define ND 48
#define NH 128
#define NW 160
#define HW (NH*NW)        /* 20480 */
#define DHW (ND*HW)       /* 983040 */
#define RATIO 8

// Scratch (device globals — no allocation allowed)
__device__ float g_feat[NV*HW*NC];          // (v, h, w, c) channels-last fp32, 13.1 MB
__device__ float g_B[(size_t)9*DHW];        // 9 hw-tap fields (kd folded), 35.4 MB
__device__ float g_pre[DHW];                // (d, h, w), 3.9 MB
__device__ float g_rot[NV][9];
__device__ float g_trans[NV][3];

// ---------------------------------------------------------------------------
// 1) Projection setup (trivial)
// ---------------------------------------------------------------------------
__global__ void proj_kernel(const float* __restrict__ proj) {
    if (threadIdx.x != 0) return;
    float comb[NV][16];
    for (int v = 0; v < NV; v++) {
        const float* E = proj + v*32;
        const float* P = proj + v*32 + 16;
        for (int r = 0; r < 3; r++)
            for (int c = 0; c < 4; c++) {
                float s = 0.f;
                for (int k = 0; k < 3; k++) s += P[r*4+k] * E[k*4+c];
                comb[v][r*4+c] = s;
            }
        for (int c = 0; c < 4; c++) comb[v][12+c] = E[12+c];
    }
    float a[4][8];
    for (int i = 0; i < 4; i++)
        for (int j = 0; j < 4; j++) { a[i][j] = comb[0][i*4+j]; a[i][4+j] = (i==j) ? 1.f : 0.f; }
    for (int col = 0; col < 4; col++) {
        int p = col;
        for (int r = col+1; r < 4; r++) if (fabsf(a[r][col]) > fabsf(a[p][col])) p = r;
        if (p != col) for (int j = 0; j < 8; j++) { float t = a[col][j]; a[col][j] = a[p][j]; a[p][j] = t; }
        float inv = 1.f / a[col][col];
        for (int j = 0; j < 8; j++) a[col][j] *= inv;
        for (int r = 0; r < 4; r++) if (r != col) {
            float f = a[r][col];
            for (int j = 0; j < 8; j++) a[r][j] -= f * a[col][j];
        }
    }
    for (int v = 1; v < NV; v++) {
        float Pm[16];
        for (int i = 0; i < 4; i++)
            for (int j = 0; j < 4; j++) {
                float s = 0.f;
                for (int k = 0; k < 4; k++) s += comb[v][i*4+k] * a[k][4+j];
                Pm[i*4+j] = s;
            }
        for (int i = 0; i < 3; i++) {
            for (int j = 0; j < 3; j++) g_rot[v][i*3+j] = Pm[i*4+j];
            g_trans[v][i] = Pm[i*4+3];
        }
    }
}

// ---------------------------------------------------------------------------
// 2) Features (V,C,H,W) -> (V,H,W,C) channels-last (fp32)
// ---------------------------------------------------------------------------
__global__ __launch_bounds__(256) void transpose_kernel(const float* __restrict__ f) {
    __shared__ float t[32][33];
    int w0 = blockIdx.x * 32, h = blockIdx.y, v = blockIdx.z;
    int tid = threadIdx.x;
    #pragma unroll
    for (int e = tid; e < 1024; e += 256) {
        int c = e >> 5, w = e & 31;
        t[c][w] = f[((size_t)(v*NC + c)*NH + h)*NW + w0 + w];
    }
    __syncthreads();
    #pragma unroll
    for (int e = tid; e < 1024; e += 256) {
        int w = e >> 5, c = e & 31;
        g_feat[((size_t)((v*NH + h)*NW) + w0 + w)*NC + c] = t[c][w];
    }
}

// ---------------------------------------------------------------------------
// 3) FUSED: warp + variance + channel contraction + conv-kd folding.
//    288 threads (9 warps), 2 CTAs/SM.  Weights live in SMEM, layout
//    [tap9][kd][32c]: warp wid reads tap9=wid -> warp-uniform LDS broadcast,
//    float4-vectorized.  No weight registers -> occupancy doubles vs R3-R6.
//    Warps 0..7: Phase A variance for 32 w-points; all 9 warps: Phase B
//    with ring accumulators folding conv's kd (9 tap-fields only).
//    Double-buffered sv, ONE barrier per depth.  No pipelining.
// ---------------------------------------------------------------------------
__global__ __launch_bounds__(288, 2) void warpvar_kernel(const float* __restrict__ dvals,
                                                         const float* __restrict__ Wreg) {
    int tid  = threadIdx.x;
    int lane = tid & 31, wid = tid >> 5;     // wid 0..8
    int sub = lane >> 3, q = lane & 7;
    int p  = wid * 4 + sub;                  // point 0..31 (warps 0..7)
    int w0 = blockIdx.x * 32;
    int h  = blockIdx.y;
    bool doA = (wid < 8);
    int w  = w0 + (doA ? p : 0);

    __shared__ float swt[9][3][NC];          // [tap9][kd][c], 3.4 KB
    __shared__ float sdep[ND];
    __shared__ float sv[2][32][33];

    for (int e = tid; e < 9*3*NC; e += 288) {
        int c = e & 31; int kd = (e >> 5) % 3; int t9 = e / 96;
        swt[t9][kd][c] = Wreg[c*27 + kd*9 + t9];
    }
    if (tid < ND) sdep[tid] = dvals[tid];

    // ---- per-view projection precompute ----
    float fw = (float)w, fh = (float)h;
    float rx[NV-1], ry[NV-1], rz[NV-1], tcx[NV-1], tcy[NV-1], tcz[NV-1];
    #pragma unroll
    for (int v = 1; v < NV; v++) {
        const float* R = g_rot[v];
        const float* T = g_trans[v];
        rx[v-1] = R[0]*fw + R[1]*fh + R[2];
        ry[v-1] = R[3]*fw + R[4]*fh + R[5];
        rz[v-1] = R[6]*fw + R[7]*fh + R[8];
        tcx[v-1] = T[0]; tcy[v-1] = T[1]; tcz[v-1] = T[2];
    }

    // ---- reference view contribution (depth-independent) ----
    const float4* f0 = (const float4*)(g_feat + (size_t)(h*NW + w)*NC) + q;
    float4 ref = *f0;
    float4 ref2 = make_float4(ref.x*ref.x, ref.y*ref.y, ref.z*ref.z, ref.w*ref.w);

    const float inv5 = 1.f / (float)NV;
    __syncthreads();   // swt + sdep ready

    auto compute_var = [&](float dep) -> float4 {
        float4 vs = ref;
        float4 vq = ref2;
        #pragma unroll
        for (int v = 0; v < NV-1; v++) {
            float px = rx[v]*dep + tcx[v];
            float py = ry[v]*dep + tcy[v];
            float pz = rz[v]*dep + tcz[v];
            float rzi = __fdividef(1.f, pz);
            float gx = px * rzi, gy = py * rzi;
            float x0f = floorf(gx), y0f = floorf(gy);
            float wx = gx - x0f, wy = gy - y0f;
            float x1f = x0f + 1.f, y1f = y0f + 1.f;
            float vx0 = (x0f >= 0.f && x0f <= (float)(NW-1)) ? 1.f : 0.f;
            float vx1 = (x1f >= 0.f && x1f <= (float)(NW-1)) ? 1.f : 0.f;
            float vy0 = (y0f >= 0.f && y0f <= (float)(NH-1)) ? 1.f : 0.f;
            float vy1 = (y1f >= 0.f && y1f <= (float)(NH-1)) ? 1.f : 0.f;
            float w00 = (1.f-wx)*(1.f-wy) * vx0 * vy0;
            float w10 = wx*(1.f-wy)       * vx1 * vy0;
            float w01 = (1.f-wx)*wy       * vx0 * vy1;
            float w11 = wx*wy             * vx1 * vy1;
            int x0 = (int)fminf(fmaxf(x0f, 0.f), (float)(NW-1));
            int x1 = (int)fminf(fmaxf(x1f, 0.f), (float)(NW-1));
            int y0 = (int)fminf(fmaxf(y0f, 0.f), (float)(NH-1));
            int y1 = (int)fminf(fmaxf(y1f, 0.f), (float)(NH-1));
            const float* base = g_feat + (size_t)(v+1)*HW*NC;
            float4 a  = ((const float4*)(base + (size_t)(y0*NW + x0)*NC))[q];
            float4 b  = ((const float4*)(base + (size_t)(y0*NW + x1)*NC))[q];
            float4 c4 = ((const float4*)(base + (size_t)(y1*NW + x0)*NC))[q];
            float4 e4 = ((const float4*)(base + (size_t)(y1*NW + x1)*NC))[q];
            float4 wv;
            wv.x = w00*a.x + w10*b.x + w01*c4.x + w11*e4.x;
            wv.y = w00*a.y + w10*b.y + w01*c4.y + w11*e4.y;
            wv.z = w00*a.z + w10*b.z + w01*c4.z + w11*e4.z;
            wv.w = w00*a.w + w10*b.w + w01*c4.w + w11*e4.w;
            vs.x += wv.x; vs.y += wv.y; vs.z += wv.z; vs.w += wv.w;
            vq.x += wv.x*wv.x; vq.y += wv.y*wv.y; vq.z += wv.z*wv.z; vq.w += wv.w*wv.w;
        }
        float mx = vs.x*inv5, my = vs.y*inv5, mz = vs.z*inv5, mw = vs.w*inv5;
        return make_float4(vq.x*inv5 - mx*mx, vq.y*inv5 - my*my,
                           vq.z*inv5 - mz*mz, vq.w*inv5 - mw*mw);
    };

    // ring accumulators for tap9 = wid
    float aP = 0.f, aC = 0.f, aN = 0.f;
    const size_t hwbase = (size_t)h*NW + w0 + lane;
    const float4* wk0 = (const float4*)&swt[wid][0][0];  // 8 float4 per kd
    const float4* wk1 = (const float4*)&swt[wid][1][0];
    const float4* wk2 = (const float4*)&swt[wid][2][0];

    for (int d = 0; d < ND; d++) {
        int buf = d & 1;
        if (doA) {
            float4 vvar = compute_var(sdep[d]);
            sv[buf][4*q+0][p] = vvar.x;
            sv[buf][4*q+1][p] = vvar.y;
            sv[buf][4*q+2][p] = vvar.z;
            sv[buf][4*q+3][p] = vvar.w;
        }
        __syncthreads();

        // Phase B: 3 kd-dots; weights via warp-uniform vectorized LDS
        float d0 = 0.f, d1 = 0.f, d2 = 0.f;
        #pragma unroll
        for (int c4 = 0; c4 < 8; c4++) {
            float f0v = sv[buf][4*c4+0][lane];
            float f1v = sv[buf][4*c4+1][lane];
            float f2v = sv[buf][4*c4+2][lane];
            float f3v = sv[buf][4*c4+3][lane];
            float4 w0 = wk0[c4], w1 = wk1[c4], w2 = wk2[c4];
            d0 += f0v*w0.x + f1v*w0.y + f2v*w0.z + f3v*w0.w;
            d1 += f0v*w1.x + f1v*w1.y + f2v*w1.z + f3v*w1.w;
            d2 += f0v*w2.x + f1v*w2.y + f2v*w2.z + f3v*w2.w;
        }
        aN += d0; aC += d1; aP += d2;     // od = d+1, d, d-1
        if (d >= 1)
            g_B[(size_t)wid*DHW + (size_t)(d-1)*HW + hwbase] = aP;
        aP = aC; aC = aN; aN = 0.f;
    }
    // od = ND-1 completes after the last input plane
    g_B[(size_t)wid*DHW + (size_t)(ND-1)*HW + hwbase] = aP;
}

// ---------------------------------------------------------------------------
// 4) 9-tap shifted sum over (h,w): pre[d,h,w] = sum_{kh,kw} B_t[d,h+kh-1,w+kw-1]
// ---------------------------------------------------------------------------
__global__ __launch_bounds__(256) void gathersum_kernel() {
    int w = blockIdx.x*32 + threadIdx.x;
    int h = blockIdx.y*8  + threadIdx.y;
    int d = blockIdx.z;
    float s = 0.f;
    #pragma unroll
    for (int kh = 0; kh < 3; kh++) {
        int hh = h + kh - 1;
        if (hh < 0 || hh >= NH) continue;
        size_t rowb = (size_t)d*HW + (size_t)hh*NW;
        #pragma unroll
        for (int kw = 0; kw < 3; kw++) {
            int ww = w + kw - 1;
            if (ww < 0 || ww >= NW) continue;
            int t = kh*3 + kw;
            s += g_B[(size_t)t*DHW + rowb + ww];
        }
    }
    g_pre[(size_t)d*HW + (size_t)h*NW + w] = s;
}

// ---------------------------------------------------------------------------
// 5) Softmax over D + depth regression + confidence
// ---------------------------------------------------------------------------
__global__ __launch_bounds__(256) void sdc_kernel(const float* __restrict__ dvals,
                                                  float* __restrict__ odepth,
                                                  float* __restrict__ oconf) {
    int idx = blockIdx.x*blockDim.x + threadIdx.x;
    if (idx >= HW) return;
    float p[ND];
    float mx = -1e30f;
    #pragma unroll
    for (int dd = 0; dd < ND; dd++) { p[dd] = g_pre[(size_t)dd*HW + idx]; mx = fmaxf(mx, p[dd]); }
    float s = 0.f;
    #pragma unroll
    for (int dd = 0; dd < ND; dd++) { p[dd] = expf(p[dd] - mx); s += p[dd]; }
    float inv = 1.f / s;
    float depth = 0.f, fi = 0.f;
    #pragma unroll
    for (int dd = 0; dd < ND; dd++) {
        float pr = p[dd] * inv;
        depth += pr * dvals[dd];
        fi    += pr * (float)dd;
    }
    int di = (int)fi;
    di = max(0, min(ND-1, di));
    float conf = 0.f;
    #pragma unroll
    for (int dd = 0; dd < ND; dd++)
        if (dd >= di-1 && dd <= di+2) conf += p[dd] * inv;
    odepth[idx] = depth;
    oconf[idx]  = conf;
}

// ---------------------------------------------------------------------------
// 6) Convex upsample x8
// ---------------------------------------------------------------------------
__global__ __launch_bounds__(256) void upsample_kernel(const float* __restrict__ mask,
                                                       const float* __restrict__ depth,
                                                       float* __restrict__ out) {
    int idx = blockIdx.x*blockDim.x + threadIdx.x;
    if (idx >= RATIO*HW) return;
    int i   = idx / HW;
    int rem = idx - i*HW;
    int h   = rem / NW;
    int w   = rem - h*NW;

    float nb[9];
    #pragma unroll
    for (int dy = 0; dy < 3; dy++)
        #pragma unroll
        for (int dx = 0; dx < 3; dx++) {
            int hh = h + dy - 1, ww = w + dx - 1;
            nb[dy*3+dx] = (hh >= 0 && hh < NH && ww >= 0 && ww < NW) ? depth[hh*NW + ww] : 0.f;
        }

    float val[8];
    #pragma unroll
    for (int j = 0; j < 8; j++) {
        float m[9]; float mx = -1e30f;
        #pragma unroll
        for (int k = 0; k < 9; k++) {
            m[k] = mask[(size_t)((k*8 + i)*8 + j)*HW + rem];
            mx = fmaxf(mx, m[k]);
        }
        float s = 0.f, acc = 0.f;
        #pragma unroll
        for (int k = 0; k < 9; k++) {
            float e = __expf(m[k] - mx);
            s += e; acc += e * nb[k];
        }
        val[j] = acc / s;
    }
    float* o = out + (size_t)(h*8 + i)*(NW*8) + w*8;
    float4* o4 = (float4*)o;
    o4[0] = make_float4(val[0], val[1], val[2], val[3]);
    o4[1] = make_float4(val[4], val[5], val[6], val[7]);
}

// ---------------------------------------------------------------------------
extern "C" void kernel_launch(void* const* d_in, const int* in_sizes, int n_in,
                              void* d_out, int out_size) {
    const float* features = (const float*)d_in[0];  // (V,B,C,H,W)
    const float* proj     = (const float*)d_in[1];  // (B,V,2,4,4)
    const float* dvals    = (const float*)d_in[2];  // (B,D)
    const float* mask     = (const float*)d_in[3];  // (B,576,H,W)
    const float* Wreg     = (const float*)d_in[4];  // (1,C,3,3,3)

    float* out       = (float*)d_out;
    float* out_depth = out + (size_t)NH*RATIO*NW*RATIO;   // after depth_up
    float* out_conf  = out_depth + HW;

    proj_kernel<<<1, 32>>>(proj);
    transpose_kernel<<<dim3(NW/32, NH, NV), 256>>>(features);
    warpvar_kernel<<<dim3(NW/32, NH), 288>>>(dvals, Wreg);
    gathersum_kernel<<<dim3(NW/32, NH/8, ND), dim3(32, 8)>>>();
    sdc_kernel<<<HW/256, 256>>>(dvals, out_depth, out_conf);
    upsample_kernel<<<(RATIO*HW)/256, 256>>>(mask, out_depth, out);
}